// round 15
// baseline (speedup 1.0000x reference)
#include <cuda_runtime.h>
#include <cuda_fp16.h>

// Problem constants
#define B_ 2
#define S_ 2048
#define E_ 2048
#define H_ 16
#define D_ 128
#define M_TOT (B_ * S_)   // 4096
#define NELEM (B_ * H_ * S_ * D_)

// Scratch (allocation-free rule: __device__ globals)
__device__ __half g_Xh[M_TOT * E_];
__device__ __half g_Wqh[E_ * E_], g_Wkh[E_ * E_], g_Wvh[E_ * E_], g_Woh[E_ * E_];
__device__ __half g_Qh[NELEM];                // [b,h,s,d], Q pre-scaled
__device__ __half g_Kh[NELEM];
__device__ __half g_Vh[NELEM];
__device__ __half g_Oh[B_ * S_ * E_];         // attn out [b,s,e]

__device__ __forceinline__ unsigned smem_u32(const void* p) {
    unsigned a;
    asm("{ .reg .u64 t; cvta.to.shared.u64 t, %1; cvt.u32.u64 %0, t; }"
        : "=r"(a) : "l"(p));
    return a;
}
__device__ __forceinline__ void cp16(unsigned dst, const void* src) {
    asm volatile("cp.async.cg.shared.global [%0], [%1], 16;"
                 :: "r"(dst), "l"(src) : "memory");
}
__device__ __forceinline__ void ldsm4(unsigned& r0, unsigned& r1,
                                      unsigned& r2, unsigned& r3, unsigned a) {
    asm volatile("ldmatrix.sync.aligned.m8n8.x4.shared.b16 {%0,%1,%2,%3}, [%4];"
                 : "=r"(r0), "=r"(r1), "=r"(r2), "=r"(r3) : "r"(a));
}
__device__ __forceinline__ void ldsm4t(unsigned& r0, unsigned& r1,
                                       unsigned& r2, unsigned& r3, unsigned a) {
    asm volatile("ldmatrix.sync.aligned.m8n8.x4.trans.shared.b16 {%0,%1,%2,%3}, [%4];"
                 : "=r"(r0), "=r"(r1), "=r"(r2), "=r"(r3) : "r"(a));
}
__device__ __forceinline__ void mma16816(float* d, const unsigned* a,
                                         unsigned b0, unsigned b1) {
    asm volatile(
        "mma.sync.aligned.m16n8k16.row.col.f32.f16.f16.f32 "
        "{%0,%1,%2,%3}, {%4,%5,%6,%7}, {%8,%9}, {%0,%1,%2,%3};"
        : "+f"(d[0]), "+f"(d[1]), "+f"(d[2]), "+f"(d[3])
        : "r"(a[0]), "r"(a[1]), "r"(a[2]), "r"(a[3]), "r"(b0), "r"(b1));
}

// ============================================================================
// Fused prep: X, Wq, Wk, Wv, Wo -> fp16 (hi). One launch.
// ============================================================================
#define XBLK (M_TOT * E_ / 1024)    // 8192
#define WBLK (E_ * E_ / 1024)       // 4096

__global__ __launch_bounds__(256)
void prep_all(const float* __restrict__ X,
              const float* __restrict__ Wq, const float* __restrict__ Wk,
              const float* __restrict__ Wv, const float* __restrict__ Wo,
              __half* __restrict__ Xh,
              __half* __restrict__ Wqh, __half* __restrict__ Wkh,
              __half* __restrict__ Wvh, __half* __restrict__ Woh) {
    const int blk = blockIdx.x;
    const float* src;
    __half* dst;
    int i;
    if (blk < XBLK) {
        src = X; dst = Xh;
        i = (blk * 256 + threadIdx.x) * 4;
    } else {
        const int wsel = (blk - XBLK) / WBLK;
        const int wb   = (blk - XBLK) % WBLK;
        src = (wsel == 0) ? Wq : (wsel == 1) ? Wk : (wsel == 2) ? Wv : Wo;
        dst = (wsel == 0) ? Wqh : (wsel == 1) ? Wkh : (wsel == 2) ? Wvh : Woh;
        i = (wb * 256 + threadIdx.x) * 4;
    }
    float4 v = *(const float4*)(src + i);
    *(__half2*)(dst + i)     = __floats2half2_rn(v.x, v.y);
    *(__half2*)(dst + i + 2) = __floats2half2_rn(v.z, v.w);
}

// ============================================================================
// GEMM core: C = Ah @ Bh^T (fp16 operands, fp32 acc).
// 128x128 tile, BK=64, 128 threads (4 warps 2x2), warp tile 64x64.
// 2-stage cp.async pipeline, ONE __syncthreads per kt (32 kt iterations).
// Smem row = 128B data + 16B pad (144 = 9*16 -> conflict-free ldmatrix).
// 73728 B smem -> 2 CTAs/SM.
// ============================================================================
#define ROWB 144
#define TILEB (128 * ROWB)          // 18432
#define ST_A 0
#define ST_B TILEB
#define STAGE (2 * TILEB)           // 36864
#define GSM (2 * STAGE)             // 73728
#define NKT 32                      // 2048 / 64

__device__ __forceinline__ void issue_stage(
    unsigned sb, int buf,
    const __half* __restrict__ A, const __half* __restrict__ Bm,
    int m0, int n0, int k0) {
    const int t = threadIdx.x;
    const unsigned base = sb + (unsigned)(buf * STAGE);
    const __half* bases[2] = { A + (size_t)m0 * E_ + k0, Bm + (size_t)n0 * E_ + k0 };
#pragma unroll
    for (int i = 0; i < 16; i++) {
        const int tile = i >> 3;
        const int rem  = t + (i & 7) * 128;   // 0..1023
        const int r    = rem >> 3;            // 0..127
        const int c    = rem & 7;             // 0..7 (16B chunks)
        cp16(base + (unsigned)(tile * TILEB + r * ROWB + c * 16),
             bases[tile] + (size_t)r * E_ + c * 8);
    }
    asm volatile("cp.async.commit_group;" ::: "memory");
}

__device__ __forceinline__ void gemm_core(
    unsigned sb,
    const __half* __restrict__ A, const __half* __restrict__ Bm,
    int m0, int n0, float acc[4][8][4]) {
    const int lane = threadIdx.x & 31;
    const int wid  = threadIdx.x >> 5;
    const int wm   = (wid & 1) * 64;
    const int wn   = (wid >> 1) * 64;
    const unsigned aoff = (unsigned)((wm + (lane & 15)) * ROWB + ((lane >> 4) << 4));
    const unsigned boff = (unsigned)((wn + (lane & 15)) * ROWB + ((lane >> 4) << 4));

#pragma unroll
    for (int i = 0; i < 4; i++)
#pragma unroll
        for (int j = 0; j < 8; j++)
#pragma unroll
            for (int c = 0; c < 4; c++) acc[i][j][c] = 0.f;

    issue_stage(sb, 0, A, Bm, m0, n0, 0);

    for (int kt = 0; kt < NKT; kt++) {
        asm volatile("cp.async.wait_group 0;" ::: "memory");
        __syncthreads();   // stage kt ready; all warps finished reading buf kt^1

        if (kt + 1 < NKT)
            issue_stage(sb, (kt + 1) & 1, A, Bm, m0, n0, (kt + 1) * 64);

        const unsigned stg = sb + (unsigned)((kt & 1) * STAGE);
#pragma unroll
        for (int ks = 0; ks < 4; ks++) {
            const unsigned kb = (unsigned)(ks * 32);   // 16 elems * 2B
            unsigned ah[4][4], bh[4][4];
#pragma unroll
            for (int i = 0; i < 4; i++) {
                const unsigned ro = (unsigned)(i * 16 * ROWB) + kb;
                ldsm4(ah[i][0], ah[i][1], ah[i][2], ah[i][3], stg + ST_A + aoff + ro);
            }
#pragma unroll
            for (int j = 0; j < 4; j++) {
                const unsigned ro = (unsigned)(j * 16 * ROWB) + kb;
                ldsm4(bh[j][0], bh[j][1], bh[j][2], bh[j][3], stg + ST_B + boff + ro);
            }
#pragma unroll
            for (int i = 0; i < 4; i++) {
#pragma unroll
                for (int j = 0; j < 4; j++) {
                    mma16816(acc[i][2 * j],     ah[i], bh[j][0], bh[j][2]);
                    mma16816(acc[i][2 * j + 1], ah[i], bh[j][1], bh[j][3]);
                }
            }
        }
    }
}

// QKV fused: blockIdx.z selects W/dest; fp16 out in [b,h,s,d].
__global__ __launch_bounds__(128, 2)
void gemm_qkv(const __half* __restrict__ Xh,
              const __half* __restrict__ Wqh, const __half* __restrict__ Wkh,
              const __half* __restrict__ Wvh,
              __half* __restrict__ Qh, __half* __restrict__ Kh,
              __half* __restrict__ Vh) {
    extern __shared__ __align__(128) char dynsm[];
    const unsigned sb = smem_u32(dynsm);
    const int z  = blockIdx.z;
    const int m0 = blockIdx.y * 128;
    const int n0 = blockIdx.x * 128;

    const __half* Bh = (z == 0) ? Wqh : (z == 1) ? Wkh : Wvh;
    __half* Ch = (z == 0) ? Qh : (z == 1) ? Kh : Vh;
    const float scale = (z == 0) ? 0.08838834764831845f : 1.0f;

    float acc[4][8][4];
    gemm_core(sb, Xh, Bh, m0, n0, acc);

    const int lane = threadIdx.x & 31;
    const int wid  = threadIdx.x >> 5;
    const int wm   = (wid & 1) * 64;
    const int wn   = (wid >> 1) * 64;
#pragma unroll
    for (int i = 0; i < 4; i++) {
        const int rg = m0 + wm + i * 16 + (lane >> 2);
#pragma unroll
        for (int j = 0; j < 8; j++) {
            const int n = n0 + wn + j * 8 + (lane & 3) * 2;
#pragma unroll
            for (int half = 0; half < 2; half++) {
                const int m = rg + half * 8;
                const float v0 = acc[i][j][2 * half + 0] * scale;
                const float v1 = acc[i][j][2 * half + 1] * scale;
                const int b = m >> 11, s = m & (S_ - 1);
                const int h = n >> 7,  d = n & (D_ - 1);
                const size_t idx = (((size_t)(b * H_ + h)) * S_ + s) * D_ + d;
                *(__half2*)(Ch + idx) = __floats2half2_rn(v0, v1);
            }
        }
    }
}

// Output projection: fp32 out [m,n] + bias.
__global__ __launch_bounds__(128, 2)
void gemm_out(const __half* __restrict__ Ahp, const __half* __restrict__ Bhp,
              const float* __restrict__ bias, float* __restrict__ C) {
    extern __shared__ __align__(128) char dynsm[];
    const unsigned sb = smem_u32(dynsm);
    const int m0 = blockIdx.y * 128;
    const int n0 = blockIdx.x * 128;

    float acc[4][8][4];
    gemm_core(sb, Ahp, Bhp, m0, n0, acc);

    const int lane = threadIdx.x & 31;
    const int wid  = threadIdx.x >> 5;
    const int wm   = (wid & 1) * 64;
    const int wn   = (wid >> 1) * 64;
#pragma unroll
    for (int i = 0; i < 4; i++) {
        const int rg = m0 + wm + i * 16 + (lane >> 2);
#pragma unroll
        for (int j = 0; j < 8; j++) {
            const int n = n0 + wn + j * 8 + (lane & 3) * 2;
            const float b0 = bias[n], b1 = bias[n + 1];
#pragma unroll
            for (int half = 0; half < 2; half++) {
                const int m = rg + half * 8;
                *(float2*)(C + (size_t)m * E_ + n) =
                    make_float2(acc[i][j][2 * half] + b0,
                                acc[i][j][2 * half + 1] + b1);
            }
        }
    }
}

// ============================================================================
// HMMA flash attention (causal, streaming softmax). BM=128, BN=64.
// Pure fp16 QK and PV. O -> fp16 [b,s,e]. (unchanged R10)
// ============================================================================
#define DP 136
#define DPB (DP * 2)
#define AQH 0
#define AKH (128 * DPB)
#define AVH (AKH + 64 * DPB)
#define ASM (AKH + 2 * 64 * DPB)     // 69632

__global__ __launch_bounds__(256, 1)
void attn_mma(const __half* __restrict__ Qh, const __half* __restrict__ Kh,
              const __half* __restrict__ Vh, __half* __restrict__ Oh) {
    extern __shared__ __align__(128) char dynsm[];
    const unsigned sb = smem_u32(dynsm);
    const int qt   = gridDim.x - 1 - blockIdx.x;
    const int bh   = blockIdx.y;
    const int t    = threadIdx.x;
    const int lane = t & 31;
    const int w    = t >> 5;

    const size_t base = (size_t)bh * S_ * D_;
    const size_t qbase = base + (size_t)qt * 128 * D_;

#pragma unroll
    for (int i = 0; i < 8; i++) {
        const int idx = t + i * 256;           // 0..2047
        const int r   = idx >> 4;
        const int d8  = (idx & 15) << 3;
        *(uint4*)(dynsm + AQH + (unsigned)(r * DPB + d8 * 2)) =
            *(const uint4*)(Qh + qbase + r * D_ + d8);
    }

    float oacc[16][4];
#pragma unroll
    for (int n = 0; n < 16; n++)
#pragma unroll
        for (int c = 0; c < 4; c++) oacc[n][c] = 0.f;
    float lsum0 = 0.f, lsum1 = 0.f;

    const int row0g = qt * 128 + w * 16 + (lane >> 2);
    const int rowmaxw = qt * 128 + w * 16 + 15;
    const unsigned qoff = (unsigned)((w * 16 + (lane & 15)) * DPB + ((lane >> 4) << 4));
    const unsigned koff = (unsigned)(((lane & 15)) * DPB + ((lane >> 4) << 4));
    const unsigned voff = (unsigned)(((lane & 7) + 8 * ((lane >> 3) & 1)) * DPB
                                     + ((lane >> 4) << 4));

    const int nkv = 2 * qt + 2;
    for (int kt = 0; kt < nkv; kt++) {
        __syncthreads();
        const size_t kb = base + (size_t)kt * 64 * D_;
#pragma unroll
        for (int i = 0; i < 4; i++) {
            const int idx = t + i * 256;       // 0..1023
            const int r   = idx >> 4;
            const int d8  = (idx & 15) << 3;
            const unsigned so = (unsigned)(r * DPB + d8 * 2);
            const size_t go = kb + r * D_ + d8;
            *(uint4*)(dynsm + AKH + so) = *(const uint4*)(Kh + go);
            *(uint4*)(dynsm + AVH + so) = *(const uint4*)(Vh + go);
        }
        __syncthreads();

        if (kt * 64 > rowmaxw) continue;

        float sf[8][4];
#pragma unroll
        for (int f = 0; f < 8; f++)
#pragma unroll
            for (int c = 0; c < 4; c++) sf[f][c] = 0.f;

#pragma unroll
        for (int ks = 0; ks < 8; ks++) {
            const unsigned kbyte = (unsigned)(ks * 32);
            unsigned aq[4];
            ldsm4(aq[0], aq[1], aq[2], aq[3], sb + AQH + qoff + kbyte);
#pragma unroll
            for (int j = 0; j < 4; j++) {
                unsigned kh[4];
                const unsigned ro = (unsigned)(j * 16 * DPB) + kbyte;
                ldsm4(kh[0], kh[1], kh[2], kh[3], sb + AKH + koff + ro);
                mma16816(sf[2 * j],     aq, kh[0], kh[2]);
                mma16816(sf[2 * j + 1], aq, kh[1], kh[3]);
            }
        }

        const bool needMask = (kt * 64 + 63) > (qt * 128 + w * 16);
        if (needMask) {
            const int colb = kt * 64 + (lane & 3) * 2;
#pragma unroll
            for (int f = 0; f < 8; f++) {
                const int col = colb + f * 8;
                sf[f][0] = (col     > row0g) ? 0.f : __expf(sf[f][0]);
                sf[f][1] = (col + 1 > row0g) ? 0.f : __expf(sf[f][1]);
                sf[f][2] = (col     > row0g + 8) ? 0.f : __expf(sf[f][2]);
                sf[f][3] = (col + 1 > row0g + 8) ? 0.f : __expf(sf[f][3]);
                lsum0 += sf[f][0] + sf[f][1];
                lsum1 += sf[f][2] + sf[f][3];
            }
        } else {
#pragma unroll
            for (int f = 0; f < 8; f++) {
                sf[f][0] = __expf(sf[f][0]);
                sf[f][1] = __expf(sf[f][1]);
                sf[f][2] = __expf(sf[f][2]);
                sf[f][3] = __expf(sf[f][3]);
                lsum0 += sf[f][0] + sf[f][1];
                lsum1 += sf[f][2] + sf[f][3];
            }
        }

#pragma unroll
        for (int j = 0; j < 4; j++) {
            unsigned ph[4];
#pragma unroll
            for (int q2 = 0; q2 < 2; q2++) {
                __half2 h01 = __floats2half2_rn(sf[2 * j + q2][0], sf[2 * j + q2][1]);
                __half2 h23 = __floats2half2_rn(sf[2 * j + q2][2], sf[2 * j + q2][3]);
                ph[2 * q2]     = *reinterpret_cast<unsigned*>(&h01);
                ph[2 * q2 + 1] = *reinterpret_cast<unsigned*>(&h23);
            }
            const unsigned vrow = (unsigned)(j * 16 * DPB);
#pragma unroll
            for (int n = 0; n < 8; n++) {
                unsigned vh[4];
                const unsigned va = vrow + (unsigned)(n * 32);
                ldsm4t(vh[0], vh[1], vh[2], vh[3], sb + AVH + voff + va);
                mma16816(oacc[2 * n],     ph, vh[0], vh[1]);
                mma16816(oacc[2 * n + 1], ph, vh[2], vh[3]);
            }
        }
    }

    lsum0 += __shfl_xor_sync(0xffffffffu, lsum0, 1);
    lsum0 += __shfl_xor_sync(0xffffffffu, lsum0, 2);
    lsum1 += __shfl_xor_sync(0xffffffffu, lsum1, 1);
    lsum1 += __shfl_xor_sync(0xffffffffu, lsum1, 2);
    const float inv0 = 1.0f / lsum0;
    const float inv1 = 1.0f / lsum1;

    const int b = bh >> 4, h = bh & 15;
    const int s0 = qt * 128 + w * 16 + (lane >> 2);
    const size_t e0 = (size_t)h * D_ + (lane & 3) * 2;
    const size_t o0 = ((size_t)b * S_ + s0) * E_ + e0;
    const size_t o1 = o0 + 8 * E_;
#pragma unroll
    for (int n = 0; n < 16; n++) {
        *(__half2*)(Oh + o0 + n * 8) =
            __floats2half2_rn(oacc[n][0] * inv0, oacc[n][1] * inv0);
        *(__half2*)(Oh + o1 + n * 8) =
            __floats2half2_rn(oacc[n][2] * inv1, oacc[n][3] * inv1);
    }
}

// ============================================================================
// Launch
// ============================================================================
extern "C" void kernel_launch(void* const* d_in, const int* in_sizes, int n_in,
                              void* d_out, int out_size) {
    const float* X  = (const float*)d_in[0];
    const float* Wq = (const float*)d_in[1];
    const float* Wk = (const float*)d_in[2];
    const float* Wv = (const float*)d_in[3];
    const float* Wo = (const float*)d_in[4];
    const float* bo = (const float*)d_in[5];

    __half *xh, *wqh, *wkh, *wvh, *woh, *qh, *kh, *vh, *oh;
    cudaGetSymbolAddress((void**)&xh, g_Xh);
    cudaGetSymbolAddress((void**)&wqh, g_Wqh); cudaGetSymbolAddress((void**)&wkh, g_Wkh);
    cudaGetSymbolAddress((void**)&wvh, g_Wvh); cudaGetSymbolAddress((void**)&woh, g_Woh);
    cudaGetSymbolAddress((void**)&qh, g_Qh);   cudaGetSymbolAddress((void**)&kh, g_Kh);
    cudaGetSymbolAddress((void**)&vh, g_Vh);   cudaGetSymbolAddress((void**)&oh, g_Oh);

    cudaFuncSetAttribute(gemm_qkv, cudaFuncAttributeMaxDynamicSharedMemorySize, GSM);
    cudaFuncSetAttribute(gemm_out, cudaFuncAttributeMaxDynamicSharedMemorySize, GSM);
    cudaFuncSetAttribute(attn_mma, cudaFuncAttributeMaxDynamicSharedMemorySize, ASM);

    // fused prep: X + 4 weights -> fp16
    prep_all<<<XBLK + 4 * WBLK, 256>>>(X, Wq, Wk, Wv, Wo,
                                       xh, wqh, wkh, wvh, woh);

    // fused QKV projections (z = 0/1/2)
    dim3 gq(E_ / 128, M_TOT / 128, 3);
    gemm_qkv<<<gq, 128, GSM>>>(xh, wqh, wkh, wvh, qh, kh, vh);

    // causal flash attention (HMMA fp16) -> [b,s,e]
    attn_mma<<<dim3(S_ / 128, B_ * H_), 256, ASM>>>(qh, kh, vh, oh);

    // output projection + bias -> d_out fp32 [b,s,e]
    dim3 gg(E_ / 128, M_TOT / 128);
    gemm_out<<<gg, 128, GSM>>>(oh, woh, bo, (float*)d_out);
}

// round 16
// speedup vs baseline: 1.0028x; 1.0028x over previous
#include <cuda_runtime.h>
#include <cuda_fp16.h>

// Problem constants
#define B_ 2
#define S_ 2048
#define E_ 2048
#define H_ 16
#define D_ 128
#define M_TOT (B_ * S_)   // 4096
#define NELEM (B_ * H_ * S_ * D_)

// Scratch (allocation-free rule: __device__ globals)
__device__ __half g_Xh[M_TOT * E_];
__device__ __half g_Wqh[E_ * E_], g_Wkh[E_ * E_], g_Wvh[E_ * E_], g_Woh[E_ * E_];
__device__ __half g_Qh[NELEM];                // [b,h,s,d], Q pre-scaled
__device__ __half g_Kh[NELEM];
__device__ __half g_Vh[NELEM];
__device__ __half g_Oh[B_ * S_ * E_];         // attn out [b,s,e]

__device__ __forceinline__ unsigned smem_u32(const void* p) {
    unsigned a;
    asm("{ .reg .u64 t; cvta.to.shared.u64 t, %1; cvt.u32.u64 %0, t; }"
        : "=r"(a) : "l"(p));
    return a;
}
__device__ __forceinline__ void cp16(unsigned dst, const void* src) {
    asm volatile("cp.async.cg.shared.global [%0], [%1], 16;"
                 :: "r"(dst), "l"(src) : "memory");
}
__device__ __forceinline__ void ldsm4(unsigned& r0, unsigned& r1,
                                      unsigned& r2, unsigned& r3, unsigned a) {
    asm volatile("ldmatrix.sync.aligned.m8n8.x4.shared.b16 {%0,%1,%2,%3}, [%4];"
                 : "=r"(r0), "=r"(r1), "=r"(r2), "=r"(r3) : "r"(a));
}
__device__ __forceinline__ void ldsm4t(unsigned& r0, unsigned& r1,
                                       unsigned& r2, unsigned& r3, unsigned a) {
    asm volatile("ldmatrix.sync.aligned.m8n8.x4.trans.shared.b16 {%0,%1,%2,%3}, [%4];"
                 : "=r"(r0), "=r"(r1), "=r"(r2), "=r"(r3) : "r"(a));
}
__device__ __forceinline__ void mma16816(float* d, const unsigned* a,
                                         unsigned b0, unsigned b1) {
    asm volatile(
        "mma.sync.aligned.m16n8k16.row.col.f32.f16.f16.f32 "
        "{%0,%1,%2,%3}, {%4,%5,%6,%7}, {%8,%9}, {%0,%1,%2,%3};"
        : "+f"(d[0]), "+f"(d[1]), "+f"(d[2]), "+f"(d[3])
        : "r"(a[0]), "r"(a[1]), "r"(a[2]), "r"(a[3]), "r"(b0), "r"(b1));
}

// ============================================================================
// Fused prep: X, Wq, Wk, Wv, Wo -> fp16 (hi). One launch.
// ============================================================================
#define XBLK (M_TOT * E_ / 1024)    // 8192
#define WBLK (E_ * E_ / 1024)       // 4096

__global__ __launch_bounds__(256)
void prep_all(const float* __restrict__ X,
              const float* __restrict__ Wq, const float* __restrict__ Wk,
              const float* __restrict__ Wv, const float* __restrict__ Wo,
              __half* __restrict__ Xh,
              __half* __restrict__ Wqh, __half* __restrict__ Wkh,
              __half* __restrict__ Wvh, __half* __restrict__ Woh) {
    const int blk = blockIdx.x;
    const float* src;
    __half* dst;
    int i;
    if (blk < XBLK) {
        src = X; dst = Xh;
        i = (blk * 256 + threadIdx.x) * 4;
    } else {
        const int wsel = (blk - XBLK) / WBLK;
        const int wb   = (blk - XBLK) % WBLK;
        src = (wsel == 0) ? Wq : (wsel == 1) ? Wk : (wsel == 2) ? Wv : Wo;
        dst = (wsel == 0) ? Wqh : (wsel == 1) ? Wkh : (wsel == 2) ? Wvh : Woh;
        i = (wb * 256 + threadIdx.x) * 4;
    }
    float4 v = *(const float4*)(src + i);
    *(__half2*)(dst + i)     = __floats2half2_rn(v.x, v.y);
    *(__half2*)(dst + i + 2) = __floats2half2_rn(v.z, v.w);
}

// ============================================================================
// GEMM core: C = Ah @ Bh^T (fp16 operands, fp32 acc).
// 128x128 tile, BK=64, 128 threads (4 warps 2x2), warp tile 64x64.
// 2-stage cp.async pipeline, ONE __syncthreads per kt (32 kt iterations).
// Smem row = 128B data + 16B pad (144 = 9*16 -> conflict-free ldmatrix).
// 73728 B smem -> 2 CTAs/SM.
// ============================================================================
#define ROWB 144
#define TILEB (128 * ROWB)          // 18432
#define ST_A 0
#define ST_B TILEB
#define STAGE (2 * TILEB)           // 36864
#define GSM (2 * STAGE)             // 73728
#define NKT 32                      // 2048 / 64

__device__ __forceinline__ void issue_stage(
    unsigned sb, int buf,
    const __half* __restrict__ A, const __half* __restrict__ Bm,
    int m0, int n0, int k0) {
    const int t = threadIdx.x;
    const unsigned base = sb + (unsigned)(buf * STAGE);
    const __half* bases[2] = { A + (size_t)m0 * E_ + k0, Bm + (size_t)n0 * E_ + k0 };
#pragma unroll
    for (int i = 0; i < 16; i++) {
        const int tile = i >> 3;
        const int rem  = t + (i & 7) * 128;   // 0..1023
        const int r    = rem >> 3;            // 0..127
        const int c    = rem & 7;             // 0..7 (16B chunks)
        cp16(base + (unsigned)(tile * TILEB + r * ROWB + c * 16),
             bases[tile] + (size_t)r * E_ + c * 8);
    }
    asm volatile("cp.async.commit_group;" ::: "memory");
}

__device__ __forceinline__ void gemm_core(
    unsigned sb,
    const __half* __restrict__ A, const __half* __restrict__ Bm,
    int m0, int n0, float acc[4][8][4]) {
    const int lane = threadIdx.x & 31;
    const int wid  = threadIdx.x >> 5;
    const int wm   = (wid & 1) * 64;
    const int wn   = (wid >> 1) * 64;
    const unsigned aoff = (unsigned)((wm + (lane & 15)) * ROWB + ((lane >> 4) << 4));
    const unsigned boff = (unsigned)((wn + (lane & 15)) * ROWB + ((lane >> 4) << 4));

#pragma unroll
    for (int i = 0; i < 4; i++)
#pragma unroll
        for (int j = 0; j < 8; j++)
#pragma unroll
            for (int c = 0; c < 4; c++) acc[i][j][c] = 0.f;

    issue_stage(sb, 0, A, Bm, m0, n0, 0);

    for (int kt = 0; kt < NKT; kt++) {
        asm volatile("cp.async.wait_group 0;" ::: "memory");
        __syncthreads();   // stage kt ready; all warps finished reading buf kt^1

        if (kt + 1 < NKT)
            issue_stage(sb, (kt + 1) & 1, A, Bm, m0, n0, (kt + 1) * 64);

        const unsigned stg = sb + (unsigned)((kt & 1) * STAGE);
#pragma unroll
        for (int ks = 0; ks < 4; ks++) {
            const unsigned kb = (unsigned)(ks * 32);   // 16 elems * 2B
            unsigned ah[4][4], bh[4][4];
#pragma unroll
            for (int i = 0; i < 4; i++) {
                const unsigned ro = (unsigned)(i * 16 * ROWB) + kb;
                ldsm4(ah[i][0], ah[i][1], ah[i][2], ah[i][3], stg + ST_A + aoff + ro);
            }
#pragma unroll
            for (int j = 0; j < 4; j++) {
                const unsigned ro = (unsigned)(j * 16 * ROWB) + kb;
                ldsm4(bh[j][0], bh[j][1], bh[j][2], bh[j][3], stg + ST_B + boff + ro);
            }
#pragma unroll
            for (int i = 0; i < 4; i++) {
#pragma unroll
                for (int j = 0; j < 4; j++) {
                    mma16816(acc[i][2 * j],     ah[i], bh[j][0], bh[j][2]);
                    mma16816(acc[i][2 * j + 1], ah[i], bh[j][1], bh[j][3]);
                }
            }
        }
    }
}

// QKV fused: blockIdx.z selects W/dest; fp16 out in [b,h,s,d].
__global__ __launch_bounds__(128, 2)
void gemm_qkv(const __half* __restrict__ Xh,
              const __half* __restrict__ Wqh, const __half* __restrict__ Wkh,
              const __half* __restrict__ Wvh,
              __half* __restrict__ Qh, __half* __restrict__ Kh,
              __half* __restrict__ Vh) {
    extern __shared__ __align__(128) char dynsm[];
    const unsigned sb = smem_u32(dynsm);
    const int z  = blockIdx.z;
    const int m0 = blockIdx.y * 128;
    const int n0 = blockIdx.x * 128;

    const __half* Bh = (z == 0) ? Wqh : (z == 1) ? Wkh : Wvh;
    __half* Ch = (z == 0) ? Qh : (z == 1) ? Kh : Vh;
    const float scale = (z == 0) ? 0.08838834764831845f : 1.0f;

    float acc[4][8][4];
    gemm_core(sb, Xh, Bh, m0, n0, acc);

    const int lane = threadIdx.x & 31;
    const int wid  = threadIdx.x >> 5;
    const int wm   = (wid & 1) * 64;
    const int wn   = (wid >> 1) * 64;
#pragma unroll
    for (int i = 0; i < 4; i++) {
        const int rg = m0 + wm + i * 16 + (lane >> 2);
#pragma unroll
        for (int j = 0; j < 8; j++) {
            const int n = n0 + wn + j * 8 + (lane & 3) * 2;
#pragma unroll
            for (int half = 0; half < 2; half++) {
                const int m = rg + half * 8;
                const float v0 = acc[i][j][2 * half + 0] * scale;
                const float v1 = acc[i][j][2 * half + 1] * scale;
                const int b = m >> 11, s = m & (S_ - 1);
                const int h = n >> 7,  d = n & (D_ - 1);
                const size_t idx = (((size_t)(b * H_ + h)) * S_ + s) * D_ + d;
                *(__half2*)(Ch + idx) = __floats2half2_rn(v0, v1);
            }
        }
    }
}

// Output projection: fp32 out [m,n] + bias.
__global__ __launch_bounds__(128, 2)
void gemm_out(const __half* __restrict__ Ahp, const __half* __restrict__ Bhp,
              const float* __restrict__ bias, float* __restrict__ C) {
    extern __shared__ __align__(128) char dynsm[];
    const unsigned sb = smem_u32(dynsm);
    const int m0 = blockIdx.y * 128;
    const int n0 = blockIdx.x * 128;

    float acc[4][8][4];
    gemm_core(sb, Ahp, Bhp, m0, n0, acc);

    const int lane = threadIdx.x & 31;
    const int wid  = threadIdx.x >> 5;
    const int wm   = (wid & 1) * 64;
    const int wn   = (wid >> 1) * 64;
#pragma unroll
    for (int i = 0; i < 4; i++) {
        const int rg = m0 + wm + i * 16 + (lane >> 2);
#pragma unroll
        for (int j = 0; j < 8; j++) {
            const int n = n0 + wn + j * 8 + (lane & 3) * 2;
            const float b0 = bias[n], b1 = bias[n + 1];
#pragma unroll
            for (int half = 0; half < 2; half++) {
                const int m = rg + half * 8;
                *(float2*)(C + (size_t)m * E_ + n) =
                    make_float2(acc[i][j][2 * half] + b0,
                                acc[i][j][2 * half + 1] + b1);
            }
        }
    }
}

// ============================================================================
// HMMA flash attention (causal, streaming softmax). BM=128, BN=64.
// Pure fp16 QK and PV. O -> fp16 [b,s,e]. (unchanged R10)
// ============================================================================
#define DP 136
#define DPB (DP * 2)
#define AQH 0
#define AKH (128 * DPB)
#define AVH (AKH + 64 * DPB)
#define ASM (AKH + 2 * 64 * DPB)     // 69632

__global__ __launch_bounds__(256, 1)
void attn_mma(const __half* __restrict__ Qh, const __half* __restrict__ Kh,
              const __half* __restrict__ Vh, __half* __restrict__ Oh) {
    extern __shared__ __align__(128) char dynsm[];
    const unsigned sb = smem_u32(dynsm);
    const int qt   = gridDim.x - 1 - blockIdx.x;
    const int bh   = blockIdx.y;
    const int t    = threadIdx.x;
    const int lane = t & 31;
    const int w    = t >> 5;

    const size_t base = (size_t)bh * S_ * D_;
    const size_t qbase = base + (size_t)qt * 128 * D_;

#pragma unroll
    for (int i = 0; i < 8; i++) {
        const int idx = t + i * 256;           // 0..2047
        const int r   = idx >> 4;
        const int d8  = (idx & 15) << 3;
        *(uint4*)(dynsm + AQH + (unsigned)(r * DPB + d8 * 2)) =
            *(const uint4*)(Qh + qbase + r * D_ + d8);
    }

    float oacc[16][4];
#pragma unroll
    for (int n = 0; n < 16; n++)
#pragma unroll
        for (int c = 0; c < 4; c++) oacc[n][c] = 0.f;
    float lsum0 = 0.f, lsum1 = 0.f;

    const int row0g = qt * 128 + w * 16 + (lane >> 2);
    const int rowmaxw = qt * 128 + w * 16 + 15;
    const unsigned qoff = (unsigned)((w * 16 + (lane & 15)) * DPB + ((lane >> 4) << 4));
    const unsigned koff = (unsigned)(((lane & 15)) * DPB + ((lane >> 4) << 4));
    const unsigned voff = (unsigned)(((lane & 7) + 8 * ((lane >> 3) & 1)) * DPB
                                     + ((lane >> 4) << 4));

    const int nkv = 2 * qt + 2;
    for (int kt = 0; kt < nkv; kt++) {
        __syncthreads();
        const size_t kb = base + (size_t)kt * 64 * D_;
#pragma unroll
        for (int i = 0; i < 4; i++) {
            const int idx = t + i * 256;       // 0..1023
            const int r   = idx >> 4;
            const int d8  = (idx & 15) << 3;
            const unsigned so = (unsigned)(r * DPB + d8 * 2);
            const size_t go = kb + r * D_ + d8;
            *(uint4*)(dynsm + AKH + so) = *(const uint4*)(Kh + go);
            *(uint4*)(dynsm + AVH + so) = *(const uint4*)(Vh + go);
        }
        __syncthreads();

        if (kt * 64 > rowmaxw) continue;

        float sf[8][4];
#pragma unroll
        for (int f = 0; f < 8; f++)
#pragma unroll
            for (int c = 0; c < 4; c++) sf[f][c] = 0.f;

#pragma unroll
        for (int ks = 0; ks < 8; ks++) {
            const unsigned kbyte = (unsigned)(ks * 32);
            unsigned aq[4];
            ldsm4(aq[0], aq[1], aq[2], aq[3], sb + AQH + qoff + kbyte);
#pragma unroll
            for (int j = 0; j < 4; j++) {
                unsigned kh[4];
                const unsigned ro = (unsigned)(j * 16 * DPB) + kbyte;
                ldsm4(kh[0], kh[1], kh[2], kh[3], sb + AKH + koff + ro);
                mma16816(sf[2 * j],     aq, kh[0], kh[2]);
                mma16816(sf[2 * j + 1], aq, kh[1], kh[3]);
            }
        }

        const bool needMask = (kt * 64 + 63) > (qt * 128 + w * 16);
        if (needMask) {
            const int colb = kt * 64 + (lane & 3) * 2;
#pragma unroll
            for (int f = 0; f < 8; f++) {
                const int col = colb + f * 8;
                sf[f][0] = (col     > row0g) ? 0.f : __expf(sf[f][0]);
                sf[f][1] = (col + 1 > row0g) ? 0.f : __expf(sf[f][1]);
                sf[f][2] = (col     > row0g + 8) ? 0.f : __expf(sf[f][2]);
                sf[f][3] = (col + 1 > row0g + 8) ? 0.f : __expf(sf[f][3]);
                lsum0 += sf[f][0] + sf[f][1];
                lsum1 += sf[f][2] + sf[f][3];
            }
        } else {
#pragma unroll
            for (int f = 0; f < 8; f++) {
                sf[f][0] = __expf(sf[f][0]);
                sf[f][1] = __expf(sf[f][1]);
                sf[f][2] = __expf(sf[f][2]);
                sf[f][3] = __expf(sf[f][3]);
                lsum0 += sf[f][0] + sf[f][1];
                lsum1 += sf[f][2] + sf[f][3];
            }
        }

#pragma unroll
        for (int j = 0; j < 4; j++) {
            unsigned ph[4];
#pragma unroll
            for (int q2 = 0; q2 < 2; q2++) {
                __half2 h01 = __floats2half2_rn(sf[2 * j + q2][0], sf[2 * j + q2][1]);
                __half2 h23 = __floats2half2_rn(sf[2 * j + q2][2], sf[2 * j + q2][3]);
                ph[2 * q2]     = *reinterpret_cast<unsigned*>(&h01);
                ph[2 * q2 + 1] = *reinterpret_cast<unsigned*>(&h23);
            }
            const unsigned vrow = (unsigned)(j * 16 * DPB);
#pragma unroll
            for (int n = 0; n < 8; n++) {
                unsigned vh[4];
                const unsigned va = vrow + (unsigned)(n * 32);
                ldsm4t(vh[0], vh[1], vh[2], vh[3], sb + AVH + voff + va);
                mma16816(oacc[2 * n],     ph, vh[0], vh[1]);
                mma16816(oacc[2 * n + 1], ph, vh[2], vh[3]);
            }
        }
    }

    lsum0 += __shfl_xor_sync(0xffffffffu, lsum0, 1);
    lsum0 += __shfl_xor_sync(0xffffffffu, lsum0, 2);
    lsum1 += __shfl_xor_sync(0xffffffffu, lsum1, 1);
    lsum1 += __shfl_xor_sync(0xffffffffu, lsum1, 2);
    const float inv0 = 1.0f / lsum0;
    const float inv1 = 1.0f / lsum1;

    const int b = bh >> 4, h = bh & 15;
    const int s0 = qt * 128 + w * 16 + (lane >> 2);
    const size_t e0 = (size_t)h * D_ + (lane & 3) * 2;
    const size_t o0 = ((size_t)b * S_ + s0) * E_ + e0;
    const size_t o1 = o0 + 8 * E_;
#pragma unroll
    for (int n = 0; n < 16; n++) {
        *(__half2*)(Oh + o0 + n * 8) =
            __floats2half2_rn(oacc[n][0] * inv0, oacc[n][1] * inv0);
        *(__half2*)(Oh + o1 + n * 8) =
            __floats2half2_rn(oacc[n][2] * inv1, oacc[n][3] * inv1);
    }
}

// ============================================================================
// Launch
// ============================================================================
extern "C" void kernel_launch(void* const* d_in, const int* in_sizes, int n_in,
                              void* d_out, int out_size) {
    const float* X  = (const float*)d_in[0];
    const float* Wq = (const float*)d_in[1];
    const float* Wk = (const float*)d_in[2];
    const float* Wv = (const float*)d_in[3];
    const float* Wo = (const float*)d_in[4];
    const float* bo = (const float*)d_in[5];

    __half *xh, *wqh, *wkh, *wvh, *woh, *qh, *kh, *vh, *oh;
    cudaGetSymbolAddress((void**)&xh, g_Xh);
    cudaGetSymbolAddress((void**)&wqh, g_Wqh); cudaGetSymbolAddress((void**)&wkh, g_Wkh);
    cudaGetSymbolAddress((void**)&wvh, g_Wvh); cudaGetSymbolAddress((void**)&woh, g_Woh);
    cudaGetSymbolAddress((void**)&qh, g_Qh);   cudaGetSymbolAddress((void**)&kh, g_Kh);
    cudaGetSymbolAddress((void**)&vh, g_Vh);   cudaGetSymbolAddress((void**)&oh, g_Oh);

    cudaFuncSetAttribute(gemm_qkv, cudaFuncAttributeMaxDynamicSharedMemorySize, GSM);
    cudaFuncSetAttribute(gemm_out, cudaFuncAttributeMaxDynamicSharedMemorySize, GSM);
    cudaFuncSetAttribute(attn_mma, cudaFuncAttributeMaxDynamicSharedMemorySize, ASM);

    // fused prep: X + 4 weights -> fp16
    prep_all<<<XBLK + 4 * WBLK, 256>>>(X, Wq, Wk, Wv, Wo,
                                       xh, wqh, wkh, wvh, woh);

    // fused QKV projections (z = 0/1/2)
    dim3 gq(E_ / 128, M_TOT / 128, 3);
    gemm_qkv<<<gq, 128, GSM>>>(xh, wqh, wkh, wvh, qh, kh, vh);

    // causal flash attention (HMMA fp16) -> [b,s,e]
    attn_mma<<<dim3(S_ / 128, B_ * H_), 256, ASM>>>(qh, kh, vh, oh);

    // output projection + bias -> d_out fp32 [b,s,e]
    dim3 gg(E_ / 128, M_TOT / 128);
    gemm_out<<<gg, 128, GSM>>>(oh, woh, bo, (float*)d_out);
}